// round 8
// baseline (speedup 1.0000x reference)
#include <cuda_runtime.h>
#include <math.h>

// Problem constants (shapes fixed by the dataset)
#define BATCH 8
#define R 300
#define C 21
#define NC 20           // foreground classes
#define KPAD 21         // output pad size == num_classes
#define RW 10           // ceil(300/32) keep-bitmask words
#define NMS_T 0.3f
#define NT 512          // threads per block
#define NW 16           // warps per block

// Cross-block intermediates (allocation-free rule: device globals)
__device__ float4   g_sb[BATCH * NC * R];      // sorted+clipped boxes per (b,class)
__device__ unsigned g_keep[BATCH * NC * RW];   // keep bitmask per (b,class)
__device__ int      g_ctr[BATCH];              // arrival counters (self-resetting)

__global__ __launch_bounds__(NT, 2) void fused_nms_kernel(
    const float* __restrict__ cls_prob,   // [B,R,C]
    const float* __restrict__ rois,       // [B,R,5]
    const float* __restrict__ bbox_pred,  // [B,R,4C]
    const float* __restrict__ im_info,    // [B,3]
    const float* __restrict__ thr_arr,    // [C]
    float* __restrict__ out, int out_size)
{
    __shared__ unsigned long long ckeys[R];   // compacted valid keys, index order
    __shared__ float4  box_sh[R];             // decoded boxes by original index
    __shared__ float4  sb_sh[R];              // boxes in sorted order (valid prefix)
    __shared__ float   area_sh[R];            // areas in sorted order
    __shared__ unsigned mask_sh[R][RW];       // suppression bitmask (valid prefix)
    __shared__ int warpcnt[NW];
    __shared__ int warpoff[NW];
    __shared__ int sV;
    __shared__ int sOld;
    // peeling-NMS state
    __shared__ unsigned slive[RW], skept[RW], sknew[RW];
    // tail selection state
    __shared__ unsigned skw_sh[NC][RW];
    __shared__ int sexcl_sh[32];

    const int blk = blockIdx.x;
    const int b   = blk / NC;
    const int cc  = blk % NC;      // 0..19
    const int c   = cc + 1;        // class id 1..20
    const int t   = threadIdx.x;
    const int lane = t & 31;
    const int wid  = t >> 5;

    const float thr = thr_arr[c];
    const float H1 = im_info[b * 3 + 0] - 1.0f;
    const float W1 = im_info[b * 3 + 1] - 1.0f;

    // ---- decode + clip + key (one row per thread; arithmetic identical to R1) ----
    int valid = 0;
    unsigned long long key = ~0ULL;
    const int r = t;
    if (r < R) {
        const float* rp = rois + (size_t)(b * R + r) * 5;
        float x1 = rp[1], y1 = rp[2], x2 = rp[3], y2 = rp[4];
        float w  = x2 - x1 + 1.0f;
        float h  = y2 - y1 + 1.0f;
        float cx = x1 + 0.5f * w;
        float cy = y1 + 0.5f * h;

        // 16B-aligned: byte offset = 336*(b*R+r) + 16*c
        const float4 d4 = *reinterpret_cast<const float4*>(
            bbox_pred + (size_t)(b * R + r) * (4 * C) + 4 * c);
        float d0 = d4.x * 0.1f;
        float d1 = d4.y * 0.1f;
        float d2 = d4.z * 0.2f;
        float d3 = d4.w * 0.2f;

        float pcx = d0 * w + cx;
        float pcy = d1 * h + cy;
        float pw  = expf(d2) * w;
        float ph  = expf(d3) * h;

        float bx1 = fminf(fmaxf(pcx - 0.5f * pw, 0.0f), W1);
        float by1 = fminf(fmaxf(pcy - 0.5f * ph, 0.0f), H1);
        float bx2 = fminf(fmaxf(pcx + 0.5f * pw, 0.0f), W1);
        float by2 = fminf(fmaxf(pcy + 0.5f * ph, 0.0f), H1);
        box_sh[r] = make_float4(bx1, by1, bx2, by2);

        float s = cls_prob[(size_t)(b * R + r) * C + c];
        valid = (s > thr) ? 1 : 0;

        // monotone float->uint, inverted => ascending sort == descending score,
        // low 32 bits = original index (stable tie-break).
        unsigned u = __float_as_uint(s);
        unsigned m = (u & 0x80000000u) ? ~u : (u | 0x80000000u);
        key = (((unsigned long long)(~m)) << 32) | (unsigned)r;
    }

    // ---- stable compaction of valid rows (index order preserved) ----
    unsigned bal = __ballot_sync(0xffffffffu, valid);
    if (lane == 0) warpcnt[wid] = __popc(bal);
    __syncthreads();
    if (t < NW) {
        int v = warpcnt[t];
        int incl = v;
        #pragma unroll
        for (int off = 1; off < NW; off <<= 1) {
            int n = __shfl_up_sync(0x0000ffffu, incl, off);
            if (t >= off) incl += n;
        }
        warpoff[t] = incl - v;
        if (t == NW - 1) sV = incl;
    }
    __syncthreads();
    const int V  = sV;
    const int VW = (V + 31) >> 5;

    if (valid) {
        int pos = warpoff[wid] + __popc(bal & ((1u << lane) - 1u));
        ckeys[pos] = key;
    }
    __syncthreads();

    // ---- enumeration (rank) sort over the V compacted keys ----
    if (V > 0) {
        if (V <= 256) {
            // 2 threads per key: even counts [0,Vh), odd counts [Vh,V)
            int p = t >> 1;
            int pc = (p < V) ? p : (V - 1);
            unsigned long long kp = ckeys[pc];
            int half = t & 1;
            int Vh = (V + 1) >> 1;
            int jlo = half ? Vh : 0;
            int jhi = half ? V : Vh;
            int rk = 0;
            #pragma unroll 4
            for (int j = jlo; j < jhi; j++)
                rk += (ckeys[j] < kp);
            rk += __shfl_xor_sync(0xffffffffu, rk, 1);
            if (half == 0 && p < V) {
                int orig = (int)(kp & 0xFFFFFFFFu);
                float4 bb = box_sh[orig];
                sb_sh[rk] = bb;
                area_sh[rk] = (bb.z - bb.x + 1.0f) * (bb.w - bb.y + 1.0f);
            }
        } else {
            if (t < V) {
                unsigned long long kp = ckeys[t];
                int rk = 0;
                #pragma unroll 4
                for (int j = 0; j < V; j++)
                    rk += (ckeys[j] < kp);
                int orig = (int)(kp & 0xFFFFFFFFu);
                float4 bb = box_sh[orig];
                sb_sh[rk] = bb;
                area_sh[rk] = (bb.z - bb.x + 1.0f) * (bb.w - bb.y + 1.0f);
            }
        }
    }
    // pre-zero mask rows (peeling reads full rows, including below-diagonal words)
    for (int idx = t; idx < V * RW; idx += NT)
        ((unsigned*)mask_sh)[idx] = 0u;
    __syncthreads();

    // ---- publish sorted boxes (valid prefix) for cross-block selection ----
    if (t < V)
        __stcg(&g_sb[(size_t)(b * NC + cc) * R + t], sb_sh[t]);

    // ---- suppression bitmask, paired rows per warp, division-free compare ----
    //   iou > T  <=>  (1+T)*inter - T*(ai+aj) > 0 (reals). When |diff| is larger
    //   than 1e-5 * union (>> combined rounding), the fast form is exact;
    //   otherwise evaluate the reference's literal (inter/union) > T.
    for (int i = wid; i < V; i += 2 * NW) {
        const int i2 = i + NW;
        const bool has2 = (i2 < V);
        float4 bi  = sb_sh[i];
        float  ai  = area_sh[i];
        float4 bi2 = sb_sh[has2 ? i2 : i];
        float  ai2 = area_sh[has2 ? i2 : i];
        for (int jw = (i >> 5); jw < VW; jw++) {
            int j  = (jw << 5) + lane;
            int jc = (j < V) ? j : (V - 1);
            float4 bj = sb_sh[jc];
            float  aj = area_sh[jc];

            bool sup1 = false, sup2 = false;
            {
                float ix1 = fmaxf(bi.x, bj.x);
                float iy1 = fmaxf(bi.y, bj.y);
                float ix2 = fminf(bi.z, bj.z);
                float iy2 = fminf(bi.w, bj.w);
                float iw = fmaxf(ix2 - ix1 + 1.0f, 0.0f);
                float ih = fmaxf(iy2 - iy1 + 1.0f, 0.0f);
                float inter = iw * ih;
                float asum = ai + aj;
                float diff = fmaf(inter, 1.0f + NMS_T, -NMS_T * asum);
                bool s1 = diff > 0.0f;
                float un = asum - inter;
                if (fabsf(diff) <= 1e-5f * un)
                    s1 = (inter / un) > NMS_T;   // rare exact fallback
                sup1 = s1 && (j > i) && (j < V);
            }
            {
                float ix1 = fmaxf(bi2.x, bj.x);
                float iy1 = fmaxf(bi2.y, bj.y);
                float ix2 = fminf(bi2.z, bj.z);
                float iy2 = fminf(bi2.w, bj.w);
                float iw = fmaxf(ix2 - ix1 + 1.0f, 0.0f);
                float ih = fmaxf(iy2 - iy1 + 1.0f, 0.0f);
                float inter = iw * ih;
                float asum = ai2 + aj;
                float diff = fmaf(inter, 1.0f + NMS_T, -NMS_T * asum);
                bool s2 = diff > 0.0f;
                float un = asum - inter;
                if (fabsf(diff) <= 1e-5f * un)
                    s2 = (inter / un) > NMS_T;   // rare exact fallback
                sup2 = s2 && has2 && (j > i2) && (j < V);
            }
            unsigned bits1 = __ballot_sync(0xffffffffu, sup1);
            unsigned bits2 = __ballot_sync(0xffffffffu, sup2);
            if (lane == 0) {
                mask_sh[i][jw] = bits1;
                if (has2) mask_sh[i2][jw] = bits2;   // zero below diagonal: harmless
            }
        }
    }

    // ---- init peeling state ----
    if (t < RW) {
        int lo = t << 5, hi = min(V, lo + 32);
        unsigned lv = 0;
        if (hi > lo) lv = (hi - lo == 32) ? 0xffffffffu : ((1u << (hi - lo)) - 1u);
        slive[t] = lv;
        skept[t] = 0u;
    }

    // ---- exact parallel peeling NMS: 2 barriers per round ----
    // Round: kn = live rows with no incoming suppression from a live earlier row
    // (greedy provably keeps these); live' = live & inc(live) & ~inc(kn).
    // __syncthreads_or doubles as the barrier and the alive-reduction.
    int alive = __syncthreads_or(V > 0);   // also orders slive/skept/mask writes
    while (alive) {
        unsigned acc = 0, nl = 0;
        if (wid < RW) {
            for (int i = lane; i < V; i += 32)
                if ((slive[i >> 5] >> (i & 31)) & 1u) acc |= mask_sh[i][wid];
            #pragma unroll
            for (int off = 16; off > 0; off >>= 1)
                acc |= __shfl_down_sync(0xffffffffu, acc, off);
            if (lane == 0) {
                unsigned kn = slive[wid] & ~acc;
                sknew[wid] = kn;
                skept[wid] |= kn;
            }
        }
        __syncthreads();                   // sknew visible; slive still old
        unsigned acc2 = 0;
        if (wid < RW) {
            for (int i = lane; i < V; i += 32)
                if ((sknew[i >> 5] >> (i & 31)) & 1u) acc2 |= mask_sh[i][wid];
            #pragma unroll
            for (int off = 16; off > 0; off >>= 1)
                acc2 |= __shfl_down_sync(0xffffffffu, acc2, off);
            if (lane == 0) {
                nl = slive[wid] & acc & ~acc2;   // acc live in lane0 register
                slive[wid] = nl;
            }
        }
        alive = __syncthreads_or(nl != 0u);  // barrier + alive reduction
    }
    if (t < RW)
        __stcg(&g_keep[(b * NC + cc) * RW + t], skept[t]);

    // ---- release writes, arrive; last block per image does selection ----
    __threadfence();
    __syncthreads();
    if (t == 0) {
        sOld = atomicAdd(&g_ctr[b], 1);
        __threadfence();
    }
    __syncthreads();

    if (sOld == NC - 1 && t < 32) {
        int cls = lane;     // 0..19 valid
        int cnt = 0;
        if (cls < NC) {
            #pragma unroll
            for (int w = 0; w < RW; w++) {
                unsigned kwv = __ldcg(&g_keep[(b * NC + cls) * RW + w]);
                skw_sh[cls][w] = kwv;
                cnt += __popc(kwv);
            }
        }
        // warp inclusive scan of counts
        int incl = cnt;
        #pragma unroll
        for (int off = 1; off < 32; off <<= 1) {
            int n = __shfl_up_sync(0xffffffffu, incl, off);
            if (lane >= off) incl += n;
        }
        int total = __shfl_sync(0xffffffffu, incl, 31);
        sexcl_sh[lane] = incl - cnt;
        __syncwarp();

        // zero this image's [K,5] slab
        for (int i = lane; i < KPAD * 5; i += 32)
            out[b * (KPAD * 5) + i] = 0.0f;
        __syncwarp();

        // slot-parallel emit: lane s owns output slot s
        int s = lane;
        int lim = min(total, KPAD);
        if (s < lim) {
            // find class: largest cl with sexcl_sh[cl] <= s (sexcl non-decreasing)
            int cl = 0;
            #pragma unroll
            for (int c2 = 1; c2 < NC; c2++)
                if (sexcl_sh[c2] <= s) cl = c2;
            int q = s - sexcl_sh[cl];
            // find q-th set bit across this class's keep words
            int w = 0;
            #pragma unroll
            for (int ww = 0; ww < RW; ww++) {
                int pc = __popc(skw_sh[cl][ww]);
                bool here = (q < pc);
                if (!here) q -= pc;
                if (here) { w = ww; break; }
            }
            unsigned word = skw_sh[cl][w];
            #pragma unroll
            for (int k = 0; k < 31; k++)
                if (k < q) word &= word - 1u;
            int bit = __ffs(word) - 1;
            float4 bb = __ldcg(&g_sb[(size_t)(b * NC + cl) * R + (w << 5) + bit]);
            float* o = out + b * (KPAD * 5) + s * 5;
            o[0] = bb.x; o[1] = bb.y; o[2] = bb.z; o[3] = bb.w;
            o[4] = (float)(cl + 1);
        }
        if (lane == 0) {
            int nbase = BATCH * KPAD * 5;
            if (out_size >= nbase + BATCH)
                out[nbase + b] = (float)lim;
            g_ctr[b] = 0;   // self-reset for next graph replay
        }
    }
}

extern "C" void kernel_launch(void* const* d_in, const int* in_sizes, int n_in,
                              void* d_out, int out_size)
{
    (void)in_sizes; (void)n_in;
    const float* cls_prob  = (const float*)d_in[0];
    const float* rois      = (const float*)d_in[1];
    const float* bbox_pred = (const float*)d_in[2];
    const float* im_info   = (const float*)d_in[3];
    const float* thr       = (const float*)d_in[4];

    fused_nms_kernel<<<BATCH * NC, NT>>>(cls_prob, rois, bbox_pred, im_info, thr,
                                         (float*)d_out, out_size);
}

// round 9
// speedup vs baseline: 1.0803x; 1.0803x over previous
#include <cuda_runtime.h>
#include <math.h>

// Problem constants (shapes fixed by the dataset)
#define BATCH 8
#define R 300
#define C 21
#define NC 20           // foreground classes
#define KPAD 21         // output pad size == num_classes
#define RW 10           // ceil(300/32) keep-bitmask words
#define NMS_T 0.3f
#define NT 1024         // threads per block (2 halves of 512)
#define HT 512          // threads per half
#define NW 16           // warps per half
#define NPAIR (NC / 2)  // class pairs per image = blocks per image

// Cross-block intermediates (allocation-free rule: device globals)
__device__ float4   g_sb[BATCH * NC * R];      // sorted+clipped boxes per (b,class)
__device__ unsigned g_keep[BATCH * NC * RW];   // keep bitmask per (b,class)
__device__ int      g_ctr[BATCH];              // arrival counters (self-resetting)

struct Smem {
    float4  box[2][R];             // decoded boxes by original index
    float4  sb[2][R];              // boxes in sorted order (valid prefix)
    unsigned long long ckeys[2][R];// compacted valid keys, index order
    float   area[2][R];            // areas in sorted order
    unsigned mask[2][R][RW];       // suppression bitmask (valid prefix)
    int warpcnt[2][NW];
    int warpoff[2][NW];
    int sV[2];
    int sOld;
    unsigned slive[2][RW], skept[2][RW], sknew[2][RW];
    unsigned skw[NC][RW];          // tail selection scratch
    int sexcl[32];
};

__global__ __launch_bounds__(NT, 1) void fused_nms_kernel(
    const float* __restrict__ cls_prob,   // [B,R,C]
    const float* __restrict__ rois,       // [B,R,5]
    const float* __restrict__ bbox_pred,  // [B,R,4C]
    const float* __restrict__ im_info,    // [B,3]
    const float* __restrict__ thr_arr,    // [C]
    float* __restrict__ out, int out_size)
{
    extern __shared__ __align__(16) unsigned char smem_raw[];
    Smem& S = *reinterpret_cast<Smem*>(smem_raw);

    const int blk  = blockIdx.x;
    const int b    = blk / NPAIR;
    const int t    = threadIdx.x;
    const int half = t >> 9;                 // 0 or 1: which class of the pair
    const int tl   = t & (HT - 1);           // thread id within half
    const int lane = t & 31;
    const int wl   = tl >> 5;                // warp id within half (0..15)
    const int cc   = (blk % NPAIR) * 2 + half;   // 0..19
    const int c    = cc + 1;                 // class id 1..20

    const float thr = thr_arr[c];
    const float H1 = im_info[b * 3 + 0] - 1.0f;
    const float W1 = im_info[b * 3 + 1] - 1.0f;

    // ---- decode + clip + key (one row per thread; arithmetic identical to R1) ----
    int valid = 0;
    unsigned long long key = ~0ULL;
    const int r = tl;
    if (r < R) {
        const float* rp = rois + (size_t)(b * R + r) * 5;
        float x1 = rp[1], y1 = rp[2], x2 = rp[3], y2 = rp[4];
        float w  = x2 - x1 + 1.0f;
        float h  = y2 - y1 + 1.0f;
        float cx = x1 + 0.5f * w;
        float cy = y1 + 0.5f * h;

        // 16B-aligned: byte offset = 336*(b*R+r) + 16*c
        const float4 d4 = *reinterpret_cast<const float4*>(
            bbox_pred + (size_t)(b * R + r) * (4 * C) + 4 * c);
        float d0 = d4.x * 0.1f;
        float d1 = d4.y * 0.1f;
        float d2 = d4.z * 0.2f;
        float d3 = d4.w * 0.2f;

        float pcx = d0 * w + cx;
        float pcy = d1 * h + cy;
        float pw  = expf(d2) * w;
        float ph  = expf(d3) * h;

        float bx1 = fminf(fmaxf(pcx - 0.5f * pw, 0.0f), W1);
        float by1 = fminf(fmaxf(pcy - 0.5f * ph, 0.0f), H1);
        float bx2 = fminf(fmaxf(pcx + 0.5f * pw, 0.0f), W1);
        float by2 = fminf(fmaxf(pcy + 0.5f * ph, 0.0f), H1);
        S.box[half][r] = make_float4(bx1, by1, bx2, by2);

        float s = cls_prob[(size_t)(b * R + r) * C + c];
        valid = (s > thr) ? 1 : 0;

        // monotone float->uint, inverted => ascending sort == descending score,
        // low 32 bits = original index (stable tie-break).
        unsigned u = __float_as_uint(s);
        unsigned m = (u & 0x80000000u) ? ~u : (u | 0x80000000u);
        key = (((unsigned long long)(~m)) << 32) | (unsigned)r;
    }

    // ---- stable compaction of valid rows per half (index order preserved) ----
    unsigned bal = __ballot_sync(0xffffffffu, valid);
    if (lane == 0) S.warpcnt[half][wl] = __popc(bal);
    __syncthreads();
    if (tl < NW) {       // lanes 0..15 of the first warp of each half
        int v = S.warpcnt[half][tl];
        int incl = v;
        #pragma unroll
        for (int off = 1; off < NW; off <<= 1) {
            int n = __shfl_up_sync(0x0000ffffu, incl, off);
            if (tl >= off) incl += n;
        }
        S.warpoff[half][tl] = incl - v;
        if (tl == NW - 1) S.sV[half] = incl;
    }
    __syncthreads();
    const int V  = S.sV[half];
    const int VW = (V + 31) >> 5;

    if (valid) {
        int pos = S.warpoff[half][wl] + __popc(bal & ((1u << lane) - 1u));
        S.ckeys[half][pos] = key;
    }
    __syncthreads();

    // ---- enumeration (rank) sort over the V compacted keys (per half) ----
    if (V > 0) {
        if (V <= 256) {
            // 2 threads per key: even counts [0,Vh), odd counts [Vh,V)
            int p = tl >> 1;
            int pc = (p < V) ? p : (V - 1);
            unsigned long long kp = S.ckeys[half][pc];
            int hh = tl & 1;
            int Vh = (V + 1) >> 1;
            int jlo = hh ? Vh : 0;
            int jhi = hh ? V : Vh;
            int rk = 0;
            #pragma unroll 4
            for (int j = jlo; j < jhi; j++)
                rk += (S.ckeys[half][j] < kp);
            rk += __shfl_xor_sync(0xffffffffu, rk, 1);
            if (hh == 0 && p < V) {
                int orig = (int)(kp & 0xFFFFFFFFu);
                float4 bb = S.box[half][orig];
                S.sb[half][rk] = bb;
                S.area[half][rk] = (bb.z - bb.x + 1.0f) * (bb.w - bb.y + 1.0f);
            }
        } else {
            if (tl < V) {
                unsigned long long kp = S.ckeys[half][tl];
                int rk = 0;
                #pragma unroll 4
                for (int j = 0; j < V; j++)
                    rk += (S.ckeys[half][j] < kp);
                int orig = (int)(kp & 0xFFFFFFFFu);
                float4 bb = S.box[half][orig];
                S.sb[half][rk] = bb;
                S.area[half][rk] = (bb.z - bb.x + 1.0f) * (bb.w - bb.y + 1.0f);
            }
        }
    }
    // pre-zero mask rows (peeling reads full rows, including below-diagonal words)
    for (int idx = tl; idx < V * RW; idx += HT)
        ((unsigned*)S.mask[half])[idx] = 0u;
    __syncthreads();

    // ---- publish sorted boxes (valid prefix) for cross-block selection ----
    if (tl < V)
        __stcg(&g_sb[(size_t)(b * NC + cc) * R + tl], S.sb[half][tl]);

    // ---- suppression bitmask, paired rows per warp, division-free compare ----
    //   iou > T  <=>  (1+T)*inter - T*(ai+aj) > 0 (reals). When |diff| is larger
    //   than 1e-5 * union (>> combined rounding), the fast form is exact;
    //   otherwise evaluate the reference's literal (inter/union) > T.
    for (int i = wl; i < V; i += 2 * NW) {
        const int i2 = i + NW;
        const bool has2 = (i2 < V);
        float4 bi  = S.sb[half][i];
        float  ai  = S.area[half][i];
        float4 bi2 = S.sb[half][has2 ? i2 : i];
        float  ai2 = S.area[half][has2 ? i2 : i];
        for (int jw = (i >> 5); jw < VW; jw++) {
            int j  = (jw << 5) + lane;
            int jc = (j < V) ? j : (V - 1);
            float4 bj = S.sb[half][jc];
            float  aj = S.area[half][jc];

            bool sup1 = false, sup2 = false;
            {
                float ix1 = fmaxf(bi.x, bj.x);
                float iy1 = fmaxf(bi.y, bj.y);
                float ix2 = fminf(bi.z, bj.z);
                float iy2 = fminf(bi.w, bj.w);
                float iw = fmaxf(ix2 - ix1 + 1.0f, 0.0f);
                float ih = fmaxf(iy2 - iy1 + 1.0f, 0.0f);
                float inter = iw * ih;
                float asum = ai + aj;
                float diff = fmaf(inter, 1.0f + NMS_T, -NMS_T * asum);
                bool s1 = diff > 0.0f;
                float un = asum - inter;
                if (fabsf(diff) <= 1e-5f * un)
                    s1 = (inter / un) > NMS_T;   // rare exact fallback
                sup1 = s1 && (j > i) && (j < V);
            }
            {
                float ix1 = fmaxf(bi2.x, bj.x);
                float iy1 = fmaxf(bi2.y, bj.y);
                float ix2 = fminf(bi2.z, bj.z);
                float iy2 = fminf(bi2.w, bj.w);
                float iw = fmaxf(ix2 - ix1 + 1.0f, 0.0f);
                float ih = fmaxf(iy2 - iy1 + 1.0f, 0.0f);
                float inter = iw * ih;
                float asum = ai2 + aj;
                float diff = fmaf(inter, 1.0f + NMS_T, -NMS_T * asum);
                bool s2 = diff > 0.0f;
                float un = asum - inter;
                if (fabsf(diff) <= 1e-5f * un)
                    s2 = (inter / un) > NMS_T;   // rare exact fallback
                sup2 = s2 && has2 && (j > i2) && (j < V);
            }
            unsigned bits1 = __ballot_sync(0xffffffffu, sup1);
            unsigned bits2 = __ballot_sync(0xffffffffu, sup2);
            if (lane == 0) {
                S.mask[half][i][jw] = bits1;
                if (has2) S.mask[half][i2][jw] = bits2;  // zero below diag: harmless
            }
        }
    }

    // ---- init peeling state ----
    if (tl < RW) {
        int lo = tl << 5, hi = min(V, lo + 32);
        unsigned lv = 0;
        if (hi > lo) lv = (hi - lo == 32) ? 0xffffffffu : ((1u << (hi - lo)) - 1u);
        S.slive[half][tl] = lv;
        S.skept[half][tl] = 0u;
    }

    // ---- exact parallel peeling NMS: 2 barriers per round (both halves) ----
    int alive = __syncthreads_or(V > 0);   // also orders slive/skept/mask writes
    while (alive) {
        unsigned acc = 0, nl = 0;
        if (wl < RW) {
            for (int i = lane; i < V; i += 32)
                if ((S.slive[half][i >> 5] >> (i & 31)) & 1u) acc |= S.mask[half][i][wl];
            #pragma unroll
            for (int off = 16; off > 0; off >>= 1)
                acc |= __shfl_down_sync(0xffffffffu, acc, off);
            if (lane == 0) {
                unsigned kn = S.slive[half][wl] & ~acc;
                S.sknew[half][wl] = kn;
                S.skept[half][wl] |= kn;
            }
        }
        __syncthreads();                   // sknew visible; slive still old
        unsigned acc2 = 0;
        if (wl < RW) {
            for (int i = lane; i < V; i += 32)
                if ((S.sknew[half][i >> 5] >> (i & 31)) & 1u) acc2 |= S.mask[half][i][wl];
            #pragma unroll
            for (int off = 16; off > 0; off >>= 1)
                acc2 |= __shfl_down_sync(0xffffffffu, acc2, off);
            if (lane == 0) {
                nl = S.slive[half][wl] & acc & ~acc2;   // acc live in lane0 register
                S.slive[half][wl] = nl;
            }
        }
        alive = __syncthreads_or(nl != 0u);  // barrier + alive reduction
    }
    if (tl < RW)
        __stcg(&g_keep[(b * NC + cc) * RW + tl], S.skept[half][tl]);

    // ---- release writes, arrive; last block per image does selection ----
    __threadfence();
    __syncthreads();
    if (t == 0) {
        S.sOld = atomicAdd(&g_ctr[b], 1);
        __threadfence();
    }
    __syncthreads();

    if (S.sOld == NPAIR - 1 && t < 32) {
        int cls = lane;     // 0..19 valid
        int cnt = 0;
        if (cls < NC) {
            #pragma unroll
            for (int w = 0; w < RW; w++) {
                unsigned kwv = __ldcg(&g_keep[(b * NC + cls) * RW + w]);
                S.skw[cls][w] = kwv;
                cnt += __popc(kwv);
            }
        }
        // warp inclusive scan of counts
        int incl = cnt;
        #pragma unroll
        for (int off = 1; off < 32; off <<= 1) {
            int n = __shfl_up_sync(0xffffffffu, incl, off);
            if (lane >= off) incl += n;
        }
        int total = __shfl_sync(0xffffffffu, incl, 31);
        S.sexcl[lane] = incl - cnt;
        __syncwarp();

        // zero this image's [K,5] slab
        for (int i = lane; i < KPAD * 5; i += 32)
            out[b * (KPAD * 5) + i] = 0.0f;
        __syncwarp();

        // slot-parallel emit: lane s owns output slot s
        int s = lane;
        int lim = min(total, KPAD);
        if (s < lim) {
            // find class: largest cl with sexcl[cl] <= s (sexcl non-decreasing)
            int cl = 0;
            #pragma unroll
            for (int c2 = 1; c2 < NC; c2++)
                if (S.sexcl[c2] <= s) cl = c2;
            int q = s - S.sexcl[cl];
            // find q-th set bit across this class's keep words
            int w = 0;
            #pragma unroll
            for (int ww = 0; ww < RW; ww++) {
                int pc = __popc(S.skw[cl][ww]);
                bool here = (q < pc);
                if (!here) q -= pc;
                if (here) { w = ww; break; }
            }
            unsigned word = S.skw[cl][w];
            #pragma unroll
            for (int k = 0; k < 31; k++)
                if (k < q) word &= word - 1u;
            int bit = __ffs(word) - 1;
            float4 bb = __ldcg(&g_sb[(size_t)(b * NC + cl) * R + (w << 5) + bit]);
            float* o = out + b * (KPAD * 5) + s * 5;
            o[0] = bb.x; o[1] = bb.y; o[2] = bb.z; o[3] = bb.w;
            o[4] = (float)(cl + 1);
        }
        if (lane == 0) {
            int nbase = BATCH * KPAD * 5;
            if (out_size >= nbase + BATCH)
                out[nbase + b] = (float)lim;
            g_ctr[b] = 0;   // self-reset for next graph replay
        }
    }
}

extern "C" void kernel_launch(void* const* d_in, const int* in_sizes, int n_in,
                              void* d_out, int out_size)
{
    (void)in_sizes; (void)n_in;
    const float* cls_prob  = (const float*)d_in[0];
    const float* rois      = (const float*)d_in[1];
    const float* bbox_pred = (const float*)d_in[2];
    const float* im_info   = (const float*)d_in[3];
    const float* thr       = (const float*)d_in[4];

    // raise dynamic smem cap (idempotent host call, capture-safe)
    cudaFuncSetAttribute(fused_nms_kernel,
                         cudaFuncAttributeMaxDynamicSharedMemorySize,
                         (int)sizeof(Smem));

    fused_nms_kernel<<<BATCH * NPAIR, NT, sizeof(Smem)>>>(
        cls_prob, rois, bbox_pred, im_info, thr, (float*)d_out, out_size);
}

// round 10
// speedup vs baseline: 1.0859x; 1.0052x over previous
#include <cuda_runtime.h>
#include <math.h>

// Problem constants (shapes fixed by the dataset)
#define BATCH 8
#define R 300
#define C 21
#define NC 20           // foreground classes
#define KPAD 21         // output pad size == num_classes
#define RW 10           // ceil(300/32) keep-bitmask words
#define NMS_T 0.3f
#define NT 1024         // threads per block (2 independent halves of 512)
#define HT 512          // threads per half
#define NW 16           // warps per half
#define NPAIR (NC / 2)  // class pairs per image = blocks per image

// Cross-block intermediates (allocation-free rule: device globals)
__device__ float4   g_sb[BATCH * NC * R];      // sorted+clipped boxes per (b,class)
__device__ unsigned g_keep[BATCH * NC * RW];   // keep bitmask per (b,class)
__device__ int      g_ctr[BATCH];              // arrival counters (self-resetting)

struct Smem {
    float4  box[2][R];             // decoded boxes by original index
    float4  sb[2][R];              // boxes in sorted order (valid prefix)
    unsigned long long ckeys[2][R];// compacted valid keys, index order
    float   area[2][R];            // areas in sorted order
    unsigned mask[2][R][RW];       // suppression bitmask (valid prefix)
    int warpcnt[2][NW];
    int warpoff[2][NW];
    int sV[2];
    int sOld[2];
    unsigned slive[2][RW], skept[2][RW], sknew[2][RW];
    unsigned skw[NC][RW];          // tail selection scratch
    int sexcl[32];
};

// Per-half barrier: ids 1 and 2 (0 is reserved for __syncthreads).
// bar.sync among 512 participating threads; shared-memory visibility included.
__device__ __forceinline__ void bar_half(int half) {
    asm volatile("bar.sync %0, %1;" :: "r"(half + 1), "r"(HT) : "memory");
}

__global__ __launch_bounds__(NT, 1) void fused_nms_kernel(
    const float* __restrict__ cls_prob,   // [B,R,C]
    const float* __restrict__ rois,       // [B,R,5]
    const float* __restrict__ bbox_pred,  // [B,R,4C]
    const float* __restrict__ im_info,    // [B,3]
    const float* __restrict__ thr_arr,    // [C]
    float* __restrict__ out, int out_size)
{
    extern __shared__ __align__(16) unsigned char smem_raw[];
    Smem& S = *reinterpret_cast<Smem*>(smem_raw);

    const int blk  = blockIdx.x;
    const int b    = blk / NPAIR;
    const int t    = threadIdx.x;
    const int half = t >> 9;                 // 0 or 1: which class of the pair
    const int tl   = t & (HT - 1);           // thread id within half
    const int lane = t & 31;
    const int wl   = tl >> 5;                // warp id within half (0..15)
    const int cc   = (blk % NPAIR) * 2 + half;   // 0..19
    const int c    = cc + 1;                 // class id 1..20

    const float thr = thr_arr[c];
    const float H1 = im_info[b * 3 + 0] - 1.0f;
    const float W1 = im_info[b * 3 + 1] - 1.0f;

    // ---- decode + clip + key (one row per thread; arithmetic identical to R1) ----
    int valid = 0;
    unsigned long long key = ~0ULL;
    const int r = tl;
    if (r < R) {
        const float* rp = rois + (size_t)(b * R + r) * 5;
        float x1 = rp[1], y1 = rp[2], x2 = rp[3], y2 = rp[4];
        float w  = x2 - x1 + 1.0f;
        float h  = y2 - y1 + 1.0f;
        float cx = x1 + 0.5f * w;
        float cy = y1 + 0.5f * h;

        // 16B-aligned: byte offset = 336*(b*R+r) + 16*c
        const float4 d4 = *reinterpret_cast<const float4*>(
            bbox_pred + (size_t)(b * R + r) * (4 * C) + 4 * c);
        float d0 = d4.x * 0.1f;
        float d1 = d4.y * 0.1f;
        float d2 = d4.z * 0.2f;
        float d3 = d4.w * 0.2f;

        float pcx = d0 * w + cx;
        float pcy = d1 * h + cy;
        float pw  = expf(d2) * w;
        float ph  = expf(d3) * h;

        float bx1 = fminf(fmaxf(pcx - 0.5f * pw, 0.0f), W1);
        float by1 = fminf(fmaxf(pcy - 0.5f * ph, 0.0f), H1);
        float bx2 = fminf(fmaxf(pcx + 0.5f * pw, 0.0f), W1);
        float by2 = fminf(fmaxf(pcy + 0.5f * ph, 0.0f), H1);
        S.box[half][r] = make_float4(bx1, by1, bx2, by2);

        float s = cls_prob[(size_t)(b * R + r) * C + c];
        valid = (s > thr) ? 1 : 0;

        // monotone float->uint, inverted => ascending sort == descending score,
        // low 32 bits = original index (stable tie-break).
        unsigned u = __float_as_uint(s);
        unsigned m = (u & 0x80000000u) ? ~u : (u | 0x80000000u);
        key = (((unsigned long long)(~m)) << 32) | (unsigned)r;
    }

    // ---- stable compaction of valid rows per half (index order preserved) ----
    unsigned bal = __ballot_sync(0xffffffffu, valid);
    if (lane == 0) S.warpcnt[half][wl] = __popc(bal);
    bar_half(half);
    if (tl < NW) {       // lanes 0..15 of warp 0 of this half
        int v = S.warpcnt[half][tl];
        int incl = v;
        #pragma unroll
        for (int off = 1; off < NW; off <<= 1) {
            int n = __shfl_up_sync(0x0000ffffu, incl, off);
            if (tl >= off) incl += n;
        }
        S.warpoff[half][tl] = incl - v;
        if (tl == NW - 1) S.sV[half] = incl;
    }
    bar_half(half);
    const int V  = S.sV[half];
    const int VW = (V + 31) >> 5;

    if (valid) {
        int pos = S.warpoff[half][wl] + __popc(bal & ((1u << lane) - 1u));
        S.ckeys[half][pos] = key;
    }
    bar_half(half);

    // ---- enumeration (rank) sort over the V compacted keys (per half) ----
    if (V > 0) {
        if (V <= 256) {
            // 2 threads per key: even counts [0,Vh), odd counts [Vh,V)
            int p = tl >> 1;
            int pc = (p < V) ? p : (V - 1);
            unsigned long long kp = S.ckeys[half][pc];
            int hh = tl & 1;
            int Vh = (V + 1) >> 1;
            int jlo = hh ? Vh : 0;
            int jhi = hh ? V : Vh;
            int rk = 0;
            #pragma unroll 4
            for (int j = jlo; j < jhi; j++)
                rk += (S.ckeys[half][j] < kp);
            rk += __shfl_xor_sync(0xffffffffu, rk, 1);
            if (hh == 0 && p < V) {
                int orig = (int)(kp & 0xFFFFFFFFu);
                float4 bb = S.box[half][orig];
                S.sb[half][rk] = bb;
                S.area[half][rk] = (bb.z - bb.x + 1.0f) * (bb.w - bb.y + 1.0f);
            }
        } else {
            if (tl < V) {
                unsigned long long kp = S.ckeys[half][tl];
                int rk = 0;
                #pragma unroll 4
                for (int j = 0; j < V; j++)
                    rk += (S.ckeys[half][j] < kp);
                int orig = (int)(kp & 0xFFFFFFFFu);
                float4 bb = S.box[half][orig];
                S.sb[half][rk] = bb;
                S.area[half][rk] = (bb.z - bb.x + 1.0f) * (bb.w - bb.y + 1.0f);
            }
        }
    }
    // pre-zero mask rows (peeling reads full rows, including below-diagonal words)
    for (int idx = tl; idx < V * RW; idx += HT)
        ((unsigned*)S.mask[half])[idx] = 0u;
    bar_half(half);

    // ---- publish sorted boxes (valid prefix) for cross-block selection ----
    if (tl < V)
        __stcg(&g_sb[(size_t)(b * NC + cc) * R + tl], S.sb[half][tl]);

    // ---- suppression bitmask, paired rows per warp, division-free compare ----
    //   iou > T  <=>  (1+T)*inter - T*(ai+aj) > 0 (reals). When |diff| is larger
    //   than 1e-5 * union (>> combined rounding), the fast form is exact;
    //   otherwise evaluate the reference's literal (inter/union) > T.
    for (int i = wl; i < V; i += 2 * NW) {
        const int i2 = i + NW;
        const bool has2 = (i2 < V);
        float4 bi  = S.sb[half][i];
        float  ai  = S.area[half][i];
        float4 bi2 = S.sb[half][has2 ? i2 : i];
        float  ai2 = S.area[half][has2 ? i2 : i];
        for (int jw = (i >> 5); jw < VW; jw++) {
            int j  = (jw << 5) + lane;
            int jc = (j < V) ? j : (V - 1);
            float4 bj = S.sb[half][jc];
            float  aj = S.area[half][jc];

            bool sup1 = false, sup2 = false;
            {
                float ix1 = fmaxf(bi.x, bj.x);
                float iy1 = fmaxf(bi.y, bj.y);
                float ix2 = fminf(bi.z, bj.z);
                float iy2 = fminf(bi.w, bj.w);
                float iw = fmaxf(ix2 - ix1 + 1.0f, 0.0f);
                float ih = fmaxf(iy2 - iy1 + 1.0f, 0.0f);
                float inter = iw * ih;
                float asum = ai + aj;
                float diff = fmaf(inter, 1.0f + NMS_T, -NMS_T * asum);
                bool s1 = diff > 0.0f;
                float un = asum - inter;
                if (fabsf(diff) <= 1e-5f * un)
                    s1 = (inter / un) > NMS_T;   // rare exact fallback
                sup1 = s1 && (j > i) && (j < V);
            }
            {
                float ix1 = fmaxf(bi2.x, bj.x);
                float iy1 = fmaxf(bi2.y, bj.y);
                float ix2 = fminf(bi2.z, bj.z);
                float iy2 = fminf(bi2.w, bj.w);
                float iw = fmaxf(ix2 - ix1 + 1.0f, 0.0f);
                float ih = fmaxf(iy2 - iy1 + 1.0f, 0.0f);
                float inter = iw * ih;
                float asum = ai2 + aj;
                float diff = fmaf(inter, 1.0f + NMS_T, -NMS_T * asum);
                bool s2 = diff > 0.0f;
                float un = asum - inter;
                if (fabsf(diff) <= 1e-5f * un)
                    s2 = (inter / un) > NMS_T;   // rare exact fallback
                sup2 = s2 && has2 && (j > i2) && (j < V);
            }
            unsigned bits1 = __ballot_sync(0xffffffffu, sup1);
            unsigned bits2 = __ballot_sync(0xffffffffu, sup2);
            if (lane == 0) {
                S.mask[half][i][jw] = bits1;
                if (has2) S.mask[half][i2][jw] = bits2;  // zero below diag: harmless
            }
        }
    }

    // ---- init peeling state ----
    if (tl < RW) {
        int lo = tl << 5, hi = min(V, lo + 32);
        unsigned lv = 0;
        if (hi > lo) lv = (hi - lo == 32) ? 0xffffffffu : ((1u << (hi - lo)) - 1u);
        S.slive[half][tl] = lv;
        S.skept[half][tl] = 0u;
    }
    bar_half(half);   // orders slive/skept/mask writes for this half

    // ---- exact parallel peeling NMS: independent per half, 2 barriers/round ----
    int alive = (V > 0);
    while (alive) {
        unsigned acc = 0;
        if (wl < RW) {
            for (int i = lane; i < V; i += 32)
                if ((S.slive[half][i >> 5] >> (i & 31)) & 1u) acc |= S.mask[half][i][wl];
            #pragma unroll
            for (int off = 16; off > 0; off >>= 1)
                acc |= __shfl_down_sync(0xffffffffu, acc, off);
            if (lane == 0) {
                unsigned kn = S.slive[half][wl] & ~acc;
                S.sknew[half][wl] = kn;
                S.skept[half][wl] |= kn;
            }
        }
        bar_half(half);                    // sknew visible; slive still old
        unsigned acc2 = 0;
        if (wl < RW) {
            for (int i = lane; i < V; i += 32)
                if ((S.sknew[half][i >> 5] >> (i & 31)) & 1u) acc2 |= S.mask[half][i][wl];
            #pragma unroll
            for (int off = 16; off > 0; off >>= 1)
                acc2 |= __shfl_down_sync(0xffffffffu, acc2, off);
            if (lane == 0)
                S.slive[half][wl] = S.slive[half][wl] & acc & ~acc2;  // acc in reg
        }
        bar_half(half);                    // updated slive visible
        unsigned any = 0;
        #pragma unroll
        for (int w2 = 0; w2 < RW; w2++) any |= S.slive[half][w2];
        alive = (any != 0u);               // uniform within the half
    }
    if (tl < RW)
        __stcg(&g_keep[(b * NC + cc) * RW + tl], S.skept[half][tl]);

    // ---- release writes, arrive; 20th-arriving half does selection ----
    __threadfence();
    bar_half(half);
    if (tl == 0) {
        S.sOld[half] = atomicAdd(&g_ctr[b], 1);
        __threadfence();
    }
    bar_half(half);

    if (S.sOld[half] == NC - 1 && tl < 32) {
        int cls = lane;     // 0..19 valid
        int cnt = 0;
        if (cls < NC) {
            #pragma unroll
            for (int w = 0; w < RW; w++) {
                unsigned kwv = __ldcg(&g_keep[(b * NC + cls) * RW + w]);
                S.skw[cls][w] = kwv;
                cnt += __popc(kwv);
            }
        }
        // warp inclusive scan of counts
        int incl = cnt;
        #pragma unroll
        for (int off = 1; off < 32; off <<= 1) {
            int n = __shfl_up_sync(0xffffffffu, incl, off);
            if (lane >= off) incl += n;
        }
        int total = __shfl_sync(0xffffffffu, incl, 31);
        S.sexcl[lane] = incl - cnt;
        __syncwarp();

        // zero this image's [K,5] slab
        for (int i = lane; i < KPAD * 5; i += 32)
            out[b * (KPAD * 5) + i] = 0.0f;
        __syncwarp();

        // slot-parallel emit: lane s owns output slot s
        int s = lane;
        int lim = min(total, KPAD);
        if (s < lim) {
            // find class: largest cl with sexcl[cl] <= s (sexcl non-decreasing)
            int cl = 0;
            #pragma unroll
            for (int c2 = 1; c2 < NC; c2++)
                if (S.sexcl[c2] <= s) cl = c2;
            int q = s - S.sexcl[cl];
            // find q-th set bit across this class's keep words
            int w = 0;
            #pragma unroll
            for (int ww = 0; ww < RW; ww++) {
                int pc = __popc(S.skw[cl][ww]);
                bool here = (q < pc);
                if (!here) q -= pc;
                if (here) { w = ww; break; }
            }
            unsigned word = S.skw[cl][w];
            #pragma unroll
            for (int k = 0; k < 31; k++)
                if (k < q) word &= word - 1u;
            int bit = __ffs(word) - 1;
            float4 bb = __ldcg(&g_sb[(size_t)(b * NC + cl) * R + (w << 5) + bit]);
            float* o = out + b * (KPAD * 5) + s * 5;
            o[0] = bb.x; o[1] = bb.y; o[2] = bb.z; o[3] = bb.w;
            o[4] = (float)(cl + 1);
        }
        if (lane == 0) {
            int nbase = BATCH * KPAD * 5;
            if (out_size >= nbase + BATCH)
                out[nbase + b] = (float)lim;
            g_ctr[b] = 0;   // self-reset for next graph replay
        }
    }
}

extern "C" void kernel_launch(void* const* d_in, const int* in_sizes, int n_in,
                              void* d_out, int out_size)
{
    (void)in_sizes; (void)n_in;
    const float* cls_prob  = (const float*)d_in[0];
    const float* rois      = (const float*)d_in[1];
    const float* bbox_pred = (const float*)d_in[2];
    const float* im_info   = (const float*)d_in[3];
    const float* thr       = (const float*)d_in[4];

    // raise dynamic smem cap (idempotent host call, capture-safe)
    cudaFuncSetAttribute(fused_nms_kernel,
                         cudaFuncAttributeMaxDynamicSharedMemorySize,
                         (int)sizeof(Smem));

    fused_nms_kernel<<<BATCH * NPAIR, NT, sizeof(Smem)>>>(
        cls_prob, rois, bbox_pred, im_info, thr, (float*)d_out, out_size);
}